// round 15
// baseline (speedup 1.0000x reference)
#include <cuda_runtime.h>
#include <stdint.h>

// Fixed problem shapes
#define TT 5
#define BB 8
#define HH 128
#define WW 128
#define HW (HH*WW)
#define C1 3
#define C2 64

#define EPS_AMB 5e-5f
#define FIXCAP (1u<<21)

// ---------------- static scratch ----------------
__device__ __align__(16) uint32_t g_base[(size_t)BB*C2*HH*4];        // AND-of-5 spike bitplanes (1 MB)
__device__ __align__(16) uint32_t g_sdel[(size_t)TT*BB*C2*HH*4];     // delta bitplanes per t (5.2 MB)
__device__ __align__(16) float    g_w2t[9*C2*C2];                    // [tap][ic][oc] fp32
__device__ __align__(16) float    g_ybase[(size_t)BB*HW*C2];         // base conv result [b][px][oc] (33.5 MB)
__device__ uint32_t g_fixcnt;
__device__ uint32_t g_fix[FIXCAP];

// ---------------- K0: W2 [oc][ic][tap] -> [tap][ic][oc] + reset counter ----------------
__global__ void k0_pack(const float* __restrict__ W2) {
    int i = blockIdx.x * 256 + threadIdx.x;
    if (i == 0) g_fixcnt = 0;
    if (i < 9*C2*C2) {
        int oc  = i / (C2*9);
        int r   = i % (C2*9);
        int ic  = r / 9;
        int tap = r % 9;
        g_w2t[(tap*C2 + ic)*C2 + oc] = W2[i];
    }
}

// ---------------- K1: conv1 + 5-step LIF1 -> base/delta bitplanes ----------------
__global__ __launch_bounds__(256) void k1_conv1_lif1(
    const float* __restrict__ x,
    const float* __restrict__ W1,
    const float* __restrict__ b1,
    const float* __restrict__ tau1p)
{
    __shared__ __align__(16) float xs[C1][10][36];
    __shared__ __align__(16) float ws[27][C2];
    __shared__ float bs[C2];

    const int tid = threadIdx.x;
    const int tx = blockIdx.x & 3;
    const int ty = blockIdx.x >> 2;
    const int b  = blockIdx.y;

    for (int i = tid; i < C2*27; i += 256) {
        int o = i / 27, r = i % 27;
        int c = r / 9, t9 = r % 9;
        ws[t9*3 + c][o] = W1[i];
    }
    if (tid < C2) bs[tid] = b1[tid];

    for (int i = tid; i < C1*10*34; i += 256) {
        int c = i / 340, r = i % 340, y = r / 34, xc = r % 34;
        int gy = ty*8 - 1 + y, gx = tx*32 - 1 + xc;
        float v = 0.f;
        if ((unsigned)gy < (unsigned)HH && (unsigned)gx < (unsigned)WW)
            v = x[((size_t)b*C1 + c)*HW + gy*WW + gx];
        xs[c][y][xc] = v;
    }
    __syncthreads();

    const int px = tid & 31, py = tid >> 5;

    float acc[C2];
    #pragma unroll
    for (int o = 0; o < C2; ++o) acc[o] = 0.f;

    #pragma unroll
    for (int dy = 0; dy < 3; ++dy)
        #pragma unroll
        for (int dx = 0; dx < 3; ++dx)
            #pragma unroll
            for (int c = 0; c < C1; ++c) {
                float xv = xs[c][py+dy][px+dx];
                const float4* wp = (const float4*)&ws[(dy*3+dx)*3 + c][0];
                #pragma unroll
                for (int q = 0; q < 16; ++q) {
                    float4 w = wp[q];
                    acc[q*4+0] = fmaf(w.x, xv, acc[q*4+0]);
                    acc[q*4+1] = fmaf(w.y, xv, acc[q*4+1]);
                    acc[q*4+2] = fmaf(w.z, xv, acc[q*4+2]);
                    acc[q*4+3] = fmaf(w.w, xv, acc[q*4+3]);
                }
            }

    float tau = tau1p[0];
    tau = fminf(fmaxf(tau, 0.5f), 5.0f);
    const float it = 1.0f / tau;
    const int gy = ty*8 + py;

    #pragma unroll
    for (int o = 0; o < C2; ++o) {
        const float xo = __fadd_rn(acc[o], bs[o]);
        float v = 0.f;
        uint32_t sh5 = 0;
        #pragma unroll
        for (int t = 0; t < TT; ++t) {
            v = __fadd_rn(v, __fmul_rn(it, __fadd_rn(xo, -v)));
            int s = (__fadd_rn(v, -0.1f) >= 0.f);
            v = s ? 0.f : fminf(fmaxf(v, -2.f), 2.f);
            sh5 |= (uint32_t)s << t;
        }
        uint32_t bsbit = (sh5 == 0x1Fu) ? 1u : 0u;
        uint32_t bw = __ballot_sync(0xffffffffu, bsbit);
        if (px == 0)
            g_base[((size_t)b*C2 + o)*HH*4 + (size_t)gy*4 + tx] = bw;
        #pragma unroll
        for (int t = 0; t < TT; ++t) {
            uint32_t db = ((sh5 >> t) & 1u) & (bsbit ^ 1u);
            uint32_t dw = __ballot_sync(0xffffffffu, db);
            if (px == 0)
                g_sdel[(((size_t)t*BB + b)*C2 + o)*HH*4 + (size_t)gy*4 + tx] = dw;
        }
    }
}

// ---------------- K2a: dense base conv (once), R4 engine ----------------
__global__ __launch_bounds__(256, 2) void k2a_base(void)
{
    __shared__ uint32_t sbits[C2*18];
    __shared__ __align__(16) float wbuf[C2*C2];

    const int tid  = threadIdx.x;
    const int warp = tid >> 5, lane = tid & 31;
    const int py  = lane >> 1;
    const int pxb = (lane & 1) * 8;
    const int ocg = warp;
    const int tx = blockIdx.x & 7, ty = blockIdx.x >> 3;
    const int b  = blockIdx.y;
    const int g0 = tx*16 - 1;
    const int w0 = g0 >> 5, off = g0 & 31;

    {
        const uint32_t* src = g_base + (size_t)b*C2*HH*4;
        for (int i = tid; i < C2*18; i += 256) {
            int ic = i / 18, y = i % 18;
            int gy = ty*16 - 1 + y;
            uint32_t val = 0;
            if ((unsigned)gy < (unsigned)HH) {
                const uint32_t* rowp = src + ((size_t)ic*HH + gy)*4;
                uint32_t lo = (w0 >= 0) ? rowp[w0] : 0u;
                uint32_t hi = (w0 + 1 <= 3) ? rowp[w0 + 1] : 0u;
                val = __funnelshift_r(lo, hi, off);
            }
            sbits[ic*18 + y] = val;
        }
    }

    float acc[64];
    #pragma unroll
    for (int i = 0; i < 64; ++i) acc[i] = 0.f;

    uint4 p0, p1, p2, p3;
    {
        const uint4* src = (const uint4*)g_w2t;
        p0 = src[tid*4]; p1 = src[tid*4+1]; p2 = src[tid*4+2]; p3 = src[tid*4+3];
    }

    for (int tap = 0; tap < 9; ++tap) {
        __syncthreads();
        ((uint4*)wbuf)[tid*4]   = p0;
        ((uint4*)wbuf)[tid*4+1] = p1;
        ((uint4*)wbuf)[tid*4+2] = p2;
        ((uint4*)wbuf)[tid*4+3] = p3;
        __syncthreads();
        if (tap < 8) {
            const uint4* src = (const uint4*)(g_w2t + (size_t)(tap+1)*C2*C2);
            p0 = src[tid*4]; p1 = src[tid*4+1]; p2 = src[tid*4+2]; p3 = src[tid*4+3];
        }

        const int dy = tap / 3, dx = tap % 3;
        const int sh = pxb + dx;
        const uint32_t* srow = sbits + (py + dy);
        const float* wt = wbuf + ocg*8;

        #pragma unroll 4
        for (int ic = 0; ic < C2; ++ic) {
            uint32_t bbits2 = srow[ic*18] >> sh;
            const float4* wp = (const float4*)(wt + ic*C2);
            float4 wa = wp[0], wb = wp[1];
            float wv[8] = {wa.x, wa.y, wa.z, wa.w, wb.x, wb.y, wb.z, wb.w};

            float sf[8];
            #pragma unroll
            for (int j = 0; j < 8; ++j)
                sf[j] = __uint_as_float(((bbits2 >> j) & 1u) * 0x3f800000u);

            #pragma unroll
            for (int o = 0; o < 8; ++o) {
                float w = wv[o];
                #pragma unroll
                for (int j = 0; j < 8; ++j)
                    acc[o*8 + j] = fmaf(w, sf[j], acc[o*8 + j]);
            }
        }
    }

    const int gy = ty*16 + py, gx0 = tx*16 + pxb;
    #pragma unroll
    for (int j = 0; j < 8; ++j) {
        float* dst = g_ybase + ((size_t)b*HW + (size_t)gy*WW + gx0 + j)*C2 + ocg*8;
        float4 r0 = make_float4(acc[0*8+j], acc[1*8+j], acc[2*8+j], acc[3*8+j]);
        float4 r1 = make_float4(acc[4*8+j], acc[5*8+j], acc[6*8+j], acc[7*8+j]);
        *(float4*)dst       = r0;
        *(float4*)(dst + 4) = r1;
    }
}

// ---------------- K2b: spike-walk delta conv + LIF2 + head (branch-free epilogue) ----------------
// dynamic smem: dbits [64][18] u32 (4608B) | da [16 warps][20 px][32 lanes] float2 (81920B) | smask (2048B)
#define DA_OFF  4608
#define SMK_OFF (DA_OFF + 16*20*32*8)
#define SMEM_K2B (SMK_OFF + 2048)

__global__ __launch_bounds__(512) void k2b_fused(
    const float* __restrict__ b2,
    const float* __restrict__ Wh,    // [3][64]
    const float* __restrict__ bh,
    const float* __restrict__ tau2p,
    float* __restrict__ out)         // [T,B,3,128,128]
{
    extern __shared__ __align__(16) uint8_t dsm[];
    uint32_t* dbits = (uint32_t*)dsm;                   // [ic][18]
    float2*   daw   = (float2*)(dsm + DA_OFF);          // [warp][20][32]
    uint32_t* smask = (uint32_t*)(dsm + SMK_OFF);       // [px][2]
    __shared__ float wh_s[3*C2];
    __shared__ float bias_s[C2];
    __shared__ float bh_s[3];

    const int tid  = threadIdx.x;
    const int warp = tid >> 5, lane = tid & 31;         // warp = output row py (0..15), lane = oc pair
    const int tx = blockIdx.x & 7, ty = blockIdx.x >> 3;
    const int b  = blockIdx.y;
    const int g0 = tx*16 - 1;
    const int w0 = g0 >> 5, off = g0 & 31;

    for (int i = tid; i < 3*C2; i += 512) wh_s[i] = Wh[i];
    if (tid < C2) bias_s[tid] = b2[tid];
    if (tid < 3)  bh_s[tid] = bh[tid];
    __syncthreads();   // bias_s/wh_s visible before register reads

    float tau = tau2p[0];
    tau = fminf(fmaxf(tau, 0.5f), 5.0f);
    const float it = 1.0f / tau;
    const float bw0 = bias_s[2*lane], bw1 = bias_s[2*lane + 1];

    const float* ybrow = g_ybase + ((size_t)b*HW + (size_t)(ty*16 + warp)*WW + tx*16)*C2 + 2*lane;
    float2* myda = daw + (size_t)warp*20*32 + lane;     // stride 32 float2 per px idx

    float v[32];
    #pragma unroll
    for (int i = 0; i < 32; ++i) v[i] = 0.f;
    uint32_t amb = 0;
    uint32_t hist[TT];
    #pragma unroll
    for (int t = 0; t < TT; ++t) hist[t] = 0;

    for (int t = 0; t < TT; ++t) {
        __syncthreads();   // prior-t consumers of dbits/smask done
        // build delta windows: 18-bit rows, bit k = input x = tx*16-1+k
        {
            const uint32_t* src = g_sdel + (size_t)(t*BB + b)*C2*HH*4;
            for (int i = tid; i < C2*18; i += 512) {
                int ic = i / 18, y = i % 18;
                int gy = ty*16 - 1 + y;
                uint32_t val = 0;
                if ((unsigned)gy < (unsigned)HH) {
                    const uint32_t* rowp = src + ((size_t)ic*HH + gy)*4;
                    uint32_t lo = (w0 >= 0) ? rowp[w0] : 0u;
                    uint32_t hi = (w0 + 1 <= 3) ? rowp[w0 + 1] : 0u;
                    val = __funnelshift_r(lo, hi, off);
                }
                dbits[ic*18 + y] = val;
            }
        }
        __syncthreads();

        // zero this warp's da tile (lane-private columns)
        #pragma unroll
        for (int i = 0; i < 20; ++i) myda[i*32] = make_float2(0.f, 0.f);

        // spike walk: window rows py..py+2, 64 ic each
        #pragma unroll
        for (int dy = 0; dy < 3; ++dy) {
            const uint32_t* wrow = dbits + (warp + dy);
            const float* wt = g_w2t + (size_t)(dy*3)*C2*C2 + 2*lane;
            #pragma unroll 1
            for (int ic = 0; ic < C2; ++ic) {
                uint32_t bits = wrow[ic*18] & 0x3FFFFu;
                if (!bits) continue;                    // single uniform branch region
                const float2 wA = __ldg((const float2*)(wt + (size_t)ic*C2));            // dx=0
                const float2 wB = __ldg((const float2*)(wt + (size_t)ic*C2 + C2*C2));    // dx=1
                const float2 wC = __ldg((const float2*)(wt + (size_t)ic*C2 + 2*C2*C2));  // dx=2
                while (bits) {                          // uniform loop over set bits
                    int k = __ffs(bits) - 1;
                    bits &= bits - 1;
                    float2 a0 = myda[(k+2)*32]; a0.x = __fadd_rn(a0.x, wA.x); a0.y = __fadd_rn(a0.y, wA.y); myda[(k+2)*32] = a0;
                    float2 a1 = myda[(k+1)*32]; a1.x = __fadd_rn(a1.x, wB.x); a1.y = __fadd_rn(a1.y, wB.y); myda[(k+1)*32] = a1;
                    float2 a2 = myda[(k  )*32]; a2.x = __fadd_rn(a2.x, wC.x); a2.y = __fadd_rn(a2.y, wC.y); myda[(k  )*32] = a2;
                }
            }
        }

        // LIF2 + spike masks (branch-free flag updates)
        #pragma unroll
        for (int c = 0; c < 16; ++c) {
            float2 bas = *(const float2*)(ybrow + (size_t)c*C2);
            float2 del = myda[(c+2)*32];
            int s0, s1;
            {
                const int slot = 2*c;
                float y = __fadd_rn(__fadd_rn(bas.x, del.x), bw0);
                float vv = __fadd_rn(v[slot], __fmul_rn(it, __fadd_rn(y, -v[slot])));
                float m = __fadd_rn(vv, -0.1f);
                s0 = (m >= 0.f);
                amb |= ((uint32_t)(fabsf(m) < EPS_AMB)) << slot;
                hist[t] |= ((uint32_t)s0 << slot);
                v[slot] = s0 ? 0.f : fminf(fmaxf(vv, -2.f), 2.f);
            }
            {
                const int slot = 2*c + 1;
                float y = __fadd_rn(__fadd_rn(bas.y, del.y), bw1);
                float vv = __fadd_rn(v[slot], __fmul_rn(it, __fadd_rn(y, -v[slot])));
                float m = __fadd_rn(vv, -0.1f);
                s1 = (m >= 0.f);
                amb |= ((uint32_t)(fabsf(m) < EPS_AMB)) << slot;
                hist[t] |= ((uint32_t)s1 << slot);
                v[slot] = s1 ? 0.f : fminf(fmaxf(vv, -2.f), 2.f);
            }
            uint32_t m0 = __ballot_sync(0xffffffffu, s0);
            uint32_t m1 = __ballot_sync(0xffffffffu, s1);
            if (lane == 0) {
                smask[(warp*16 + c)*2]     = m0;
                smask[(warp*16 + c)*2 + 1] = m1;
            }
        }
        __syncthreads();

        // head: 256 threads, one pixel each — BRANCH-FREE predicated FMA chain,
        // bit-identical to the ascending-oc FADD chain (fmaf(0,w,o)==o, fmaf(1,w,o)==RN(o+w))
        if (tid < 256) {
            const int px = tid;
            uint32_t m0 = smask[px*2], m1 = smask[px*2 + 1];
            float o0 = 0.f, o1 = 0.f, o2 = 0.f;
            #pragma unroll
            for (int l = 0; l < 32; ++l) {
                float f0 = __uint_as_float(((m0 >> l) & 1u) * 0x3f800000u);
                float f1 = __uint_as_float(((m1 >> l) & 1u) * 0x3f800000u);
                o0 = fmaf(f0, wh_s[2*l], o0);
                o1 = fmaf(f0, wh_s[C2 + 2*l], o1);
                o2 = fmaf(f0, wh_s[2*C2 + 2*l], o2);
                o0 = fmaf(f1, wh_s[2*l + 1], o0);
                o1 = fmaf(f1, wh_s[C2 + 2*l + 1], o1);
                o2 = fmaf(f1, wh_s[2*C2 + 2*l + 1], o2);
            }
            const int gy = ty*16 + (px >> 4), gx = tx*16 + (px & 15);
            size_t ob = ((size_t)(t*BB + b)*3)*HW + (size_t)gy*WW + gx;
            out[ob]        = __fadd_rn(o0, bh_s[0]);
            out[ob +  HW]  = __fadd_rn(o1, bh_s[1]);
            out[ob + 2*HW] = __fadd_rn(o2, bh_s[2]);
        }
    }

    // emit fixup records for ambiguous slots
    if (amb) {
        #pragma unroll
        for (int slot = 0; slot < 32; ++slot) {
            if ((amb >> slot) & 1u) {
                const int oc = 2*lane + (slot & 1);
                const int c  = slot >> 1;
                const int gy = ty*16 + warp, gx = tx*16 + c;
                uint32_t sh5 = 0;
                #pragma unroll
                for (int t = 0; t < TT; ++t) sh5 |= ((hist[t] >> slot) & 1u) << t;
                uint32_t rec = (uint32_t)(gy*WW + gx) | ((uint32_t)oc << 14)
                             | ((uint32_t)b << 20) | (sh5 << 23);
                uint32_t idx = atomicAdd(&g_fixcnt, 1u);
                if (idx < FIXCAP) g_fix[idx] = rec;
            }
        }
    }
}

// ---------------- K3: warp-cooperative, ORDER-EXACT fp32 replay of ambiguous elements ----------------
__global__ __launch_bounds__(128) void k3_fixup(
    const float* __restrict__ b2,
    const float* __restrict__ Wh,
    const float* __restrict__ tau2p,
    float* __restrict__ out)
{
    uint32_t cnt = g_fixcnt;
    if (cnt > FIXCAP) cnt = FIXCAP;

    const int lane = threadIdx.x & 31;
    const uint32_t wid = (blockIdx.x * blockDim.x + threadIdx.x) >> 5;
    const uint32_t nw  = (gridDim.x * blockDim.x) >> 5;

    float tau = tau2p[0];
    tau = fminf(fmaxf(tau, 0.5f), 5.0f);
    const float it = 1.0f / tau;

    for (uint32_t i = wid; i < cnt; i += nw) {
        uint32_t rec = g_fix[i];
        int pixel = rec & 16383;
        int oc    = (rec >> 14) & 63;
        int b     = (rec >> 20) & 7;
        uint32_t sh = (rec >> 23) & 31;
        int py = pixel >> 7, px = pixel & 127;

        const int ic0 = lane, ic1 = lane + 32;
        float wt0[9], wt1[9];
        #pragma unroll
        for (int tap = 0; tap < 9; ++tap) {
            wt0[tap] = g_w2t[((size_t)tap*C2 + ic0)*C2 + oc];
            wt1[tap] = g_w2t[((size_t)tap*C2 + ic1)*C2 + oc];
        }

        const uint32_t* bbase = g_base + (size_t)b*C2*HH*4;
        float v = 0.f;
        const float bia = b2[oc];

        for (int t = 0; t < TT; ++t) {
            const uint32_t* dbase = g_sdel + (size_t)(t*BB + b)*C2*HH*4;
            float acc = 0.f;
            #pragma unroll
            for (int tap = 0; tap < 9; ++tap) {
                int dy = tap / 3, dx = tap % 3;
                int gy = py + dy - 1, gx = px + dx - 1;
                if ((unsigned)gy < (unsigned)HH && (unsigned)gx < (unsigned)WW) {
                    int wi = gx >> 5, offb = gx & 31;
                    size_t ro = (size_t)gy*4 + wi;
                    uint32_t wd0 = bbase[(size_t)ic0*HH*4 + ro] | dbase[(size_t)ic0*HH*4 + ro];
                    uint32_t wd1 = bbase[(size_t)ic1*HH*4 + ro] | dbase[(size_t)ic1*HH*4 + ro];
                    uint32_t m0 = __ballot_sync(0xffffffffu, (wd0 >> offb) & 1u);
                    uint32_t m1 = __ballot_sync(0xffffffffu, (wd1 >> offb) & 1u);
                    while (m0) {            // uniform: ascending ic 0..31
                        int j = __ffs(m0) - 1; m0 &= m0 - 1;
                        float w = __shfl_sync(0xffffffffu, wt0[tap], j);
                        acc = __fadd_rn(acc, w);
                    }
                    while (m1) {            // uniform: ascending ic 32..63
                        int j = __ffs(m1) - 1; m1 &= m1 - 1;
                        float w = __shfl_sync(0xffffffffu, wt1[tap], j);
                        acc = __fadd_rn(acc, w);
                    }
                }
            }
            float y = __fadd_rn(acc, bia);
            float vv = __fadd_rn(v, __fmul_rn(it, __fadd_rn(y, -v)));
            int s = (__fadd_rn(vv, -0.1f) >= 0.f);
            v = s ? 0.f : fminf(fmaxf(vv, -2.f), 2.f);

            int s_h = (sh >> t) & 1;
            if (s != s_h && lane == 0) {
                float d = s ? 1.f : -1.f;
                #pragma unroll
                for (int ch = 0; ch < 3; ++ch)
                    atomicAdd(&out[((size_t)(t*BB + b)*3 + ch)*HW + pixel], d * Wh[ch*C2 + oc]);
            }
        }
    }
}

// ---------------- launch ----------------
extern "C" void kernel_launch(void* const* d_in, const int* in_sizes, int n_in,
                              void* d_out, int out_size)
{
    const float* lr_lab = (const float*)d_in[0];
    const float* W1     = (const float*)d_in[1];
    const float* b1     = (const float*)d_in[2];
    const float* tau1   = (const float*)d_in[3];
    const float* W2     = (const float*)d_in[4];
    const float* b2     = (const float*)d_in[5];
    const float* tau2   = (const float*)d_in[6];
    const float* Wh     = (const float*)d_in[7];
    const float* bh     = (const float*)d_in[8];
    float* out = (float*)d_out;

    cudaFuncSetAttribute(k2b_fused, cudaFuncAttributeMaxDynamicSharedMemorySize, SMEM_K2B);

    k0_pack<<<(9*C2*C2 + 255)/256, 256>>>(W2);
    k1_conv1_lif1<<<dim3(64, BB), 256>>>(lr_lab, W1, b1, tau1);
    k2a_base<<<dim3(64, BB), 256>>>();
    k2b_fused<<<dim3(64, BB), 512, SMEM_K2B>>>(b2, Wh, bh, tau2, out);
    k3_fixup<<<2048, 128>>>(b2, Wh, tau2, out);
}

// round 16
// speedup vs baseline: 1.1037x; 1.1037x over previous
#include <cuda_runtime.h>
#include <stdint.h>

// Fixed problem shapes
#define TT 5
#define BB 8
#define HH 128
#define WW 128
#define HW (HH*WW)
#define C1 3
#define C2 64

#define EPS_AMB 5e-5f
#define FIXCAP (1u<<21)

// ---------------- static scratch ----------------
__device__ __align__(16) uint32_t g_base[(size_t)BB*C2*HH*4];        // AND-of-5 spike bitplanes (1 MB)
__device__ __align__(16) uint32_t g_sdel[(size_t)TT*BB*C2*HH*4];     // delta bitplanes per t (5.2 MB)
__device__ __align__(16) float    g_w2t[9*C2*C2];                    // [tap][ic][oc] fp32
__device__ __align__(16) float    g_ybase[(size_t)BB*HW*C2];         // base conv result [b][px][oc] (33.5 MB)
__device__ uint32_t g_fixcnt;
__device__ uint32_t g_fix[FIXCAP];

// ---------------- K0: W2 [oc][ic][tap] -> [tap][ic][oc] + reset counter ----------------
__global__ void k0_pack(const float* __restrict__ W2) {
    int i = blockIdx.x * 256 + threadIdx.x;
    if (i == 0) g_fixcnt = 0;
    if (i < 9*C2*C2) {
        int oc  = i / (C2*9);
        int r   = i % (C2*9);
        int ic  = r / 9;
        int tap = r % 9;
        g_w2t[(tap*C2 + ic)*C2 + oc] = W2[i];
    }
}

// ---------------- K1: conv1 + 5-step LIF1 -> base/delta bitplanes ----------------
__global__ __launch_bounds__(256) void k1_conv1_lif1(
    const float* __restrict__ x,
    const float* __restrict__ W1,
    const float* __restrict__ b1,
    const float* __restrict__ tau1p)
{
    __shared__ __align__(16) float xs[C1][10][36];
    __shared__ __align__(16) float ws[27][C2];
    __shared__ float bs[C2];

    const int tid = threadIdx.x;
    const int tx = blockIdx.x & 3;
    const int ty = blockIdx.x >> 2;
    const int b  = blockIdx.y;

    for (int i = tid; i < C2*27; i += 256) {
        int o = i / 27, r = i % 27;
        int c = r / 9, t9 = r % 9;
        ws[t9*3 + c][o] = W1[i];
    }
    if (tid < C2) bs[tid] = b1[tid];

    for (int i = tid; i < C1*10*34; i += 256) {
        int c = i / 340, r = i % 340, y = r / 34, xc = r % 34;
        int gy = ty*8 - 1 + y, gx = tx*32 - 1 + xc;
        float v = 0.f;
        if ((unsigned)gy < (unsigned)HH && (unsigned)gx < (unsigned)WW)
            v = x[((size_t)b*C1 + c)*HW + gy*WW + gx];
        xs[c][y][xc] = v;
    }
    __syncthreads();

    const int px = tid & 31, py = tid >> 5;

    float acc[C2];
    #pragma unroll
    for (int o = 0; o < C2; ++o) acc[o] = 0.f;

    #pragma unroll
    for (int dy = 0; dy < 3; ++dy)
        #pragma unroll
        for (int dx = 0; dx < 3; ++dx)
            #pragma unroll
            for (int c = 0; c < C1; ++c) {
                float xv = xs[c][py+dy][px+dx];
                const float4* wp = (const float4*)&ws[(dy*3+dx)*3 + c][0];
                #pragma unroll
                for (int q = 0; q < 16; ++q) {
                    float4 w = wp[q];
                    acc[q*4+0] = fmaf(w.x, xv, acc[q*4+0]);
                    acc[q*4+1] = fmaf(w.y, xv, acc[q*4+1]);
                    acc[q*4+2] = fmaf(w.z, xv, acc[q*4+2]);
                    acc[q*4+3] = fmaf(w.w, xv, acc[q*4+3]);
                }
            }

    float tau = tau1p[0];
    tau = fminf(fmaxf(tau, 0.5f), 5.0f);
    const float it = 1.0f / tau;
    const int gy = ty*8 + py;

    #pragma unroll
    for (int o = 0; o < C2; ++o) {
        const float xo = __fadd_rn(acc[o], bs[o]);
        float v = 0.f;
        uint32_t sh5 = 0;
        #pragma unroll
        for (int t = 0; t < TT; ++t) {
            v = __fadd_rn(v, __fmul_rn(it, __fadd_rn(xo, -v)));
            int s = (__fadd_rn(v, -0.1f) >= 0.f);
            v = s ? 0.f : fminf(fmaxf(v, -2.f), 2.f);
            sh5 |= (uint32_t)s << t;
        }
        uint32_t bsbit = (sh5 == 0x1Fu) ? 1u : 0u;
        uint32_t bw = __ballot_sync(0xffffffffu, bsbit);
        if (px == 0)
            g_base[((size_t)b*C2 + o)*HH*4 + (size_t)gy*4 + tx] = bw;
        #pragma unroll
        for (int t = 0; t < TT; ++t) {
            uint32_t db = ((sh5 >> t) & 1u) & (bsbit ^ 1u);
            uint32_t dw = __ballot_sync(0xffffffffu, db);
            if (px == 0)
                g_sdel[(((size_t)t*BB + b)*C2 + o)*HH*4 + (size_t)gy*4 + tx] = dw;
        }
    }
}

// ---------------- K2a: dense base conv (once), R4 engine ----------------
__global__ __launch_bounds__(256, 2) void k2a_base(void)
{
    __shared__ uint32_t sbits[C2*18];
    __shared__ __align__(16) float wbuf[C2*C2];

    const int tid  = threadIdx.x;
    const int warp = tid >> 5, lane = tid & 31;
    const int py  = lane >> 1;
    const int pxb = (lane & 1) * 8;
    const int ocg = warp;
    const int tx = blockIdx.x & 7, ty = blockIdx.x >> 3;
    const int b  = blockIdx.y;
    const int g0 = tx*16 - 1;
    const int w0 = g0 >> 5, off = g0 & 31;

    {
        const uint32_t* src = g_base + (size_t)b*C2*HH*4;
        for (int i = tid; i < C2*18; i += 256) {
            int ic = i / 18, y = i % 18;
            int gy = ty*16 - 1 + y;
            uint32_t val = 0;
            if ((unsigned)gy < (unsigned)HH) {
                const uint32_t* rowp = src + ((size_t)ic*HH + gy)*4;
                uint32_t lo = (w0 >= 0) ? rowp[w0] : 0u;
                uint32_t hi = (w0 + 1 <= 3) ? rowp[w0 + 1] : 0u;
                val = __funnelshift_r(lo, hi, off);
            }
            sbits[ic*18 + y] = val;
        }
    }

    float acc[64];
    #pragma unroll
    for (int i = 0; i < 64; ++i) acc[i] = 0.f;

    uint4 p0, p1, p2, p3;
    {
        const uint4* src = (const uint4*)g_w2t;
        p0 = src[tid*4]; p1 = src[tid*4+1]; p2 = src[tid*4+2]; p3 = src[tid*4+3];
    }

    for (int tap = 0; tap < 9; ++tap) {
        __syncthreads();
        ((uint4*)wbuf)[tid*4]   = p0;
        ((uint4*)wbuf)[tid*4+1] = p1;
        ((uint4*)wbuf)[tid*4+2] = p2;
        ((uint4*)wbuf)[tid*4+3] = p3;
        __syncthreads();
        if (tap < 8) {
            const uint4* src = (const uint4*)(g_w2t + (size_t)(tap+1)*C2*C2);
            p0 = src[tid*4]; p1 = src[tid*4+1]; p2 = src[tid*4+2]; p3 = src[tid*4+3];
        }

        const int dy = tap / 3, dx = tap % 3;
        const int sh = pxb + dx;
        const uint32_t* srow = sbits + (py + dy);
        const float* wt = wbuf + ocg*8;

        #pragma unroll 4
        for (int ic = 0; ic < C2; ++ic) {
            uint32_t bbits2 = srow[ic*18] >> sh;
            const float4* wp = (const float4*)(wt + ic*C2);
            float4 wa = wp[0], wb = wp[1];
            float wv[8] = {wa.x, wa.y, wa.z, wa.w, wb.x, wb.y, wb.z, wb.w};

            float sf[8];
            #pragma unroll
            for (int j = 0; j < 8; ++j)
                sf[j] = __uint_as_float(((bbits2 >> j) & 1u) * 0x3f800000u);

            #pragma unroll
            for (int o = 0; o < 8; ++o) {
                float w = wv[o];
                #pragma unroll
                for (int j = 0; j < 8; ++j)
                    acc[o*8 + j] = fmaf(w, sf[j], acc[o*8 + j]);
            }
        }
    }

    const int gy = ty*16 + py, gx0 = tx*16 + pxb;
    #pragma unroll
    for (int j = 0; j < 8; ++j) {
        float* dst = g_ybase + ((size_t)b*HW + (size_t)gy*WW + gx0 + j)*C2 + ocg*8;
        float4 r0 = make_float4(acc[0*8+j], acc[1*8+j], acc[2*8+j], acc[3*8+j]);
        float4 r1 = make_float4(acc[4*8+j], acc[5*8+j], acc[6*8+j], acc[7*8+j]);
        *(float4*)dst       = r0;
        *(float4*)(dst + 4) = r1;
    }
}

// ---------------- K2b: spike-walk delta conv + LIF2 + head — 8-row bands for occupancy ----------------
// block 256 (8 warps = 8 rows), grid (128 tiles, 8 b)
// dynamic smem: dbits [64][10] u32 (2560B) | da [8 warps][20 px][32 lanes] float2 (40960B) | smask [128][2] (1024B)
#define DA_OFF  2560
#define SMK_OFF (DA_OFF + 8*20*32*8)
#define SMEM_K2B (SMK_OFF + 1024)

__global__ __launch_bounds__(256, 3) void k2b_fused(
    const float* __restrict__ b2,
    const float* __restrict__ Wh,    // [3][64]
    const float* __restrict__ bh,
    const float* __restrict__ tau2p,
    float* __restrict__ out)         // [T,B,3,128,128]
{
    extern __shared__ __align__(16) uint8_t dsm[];
    uint32_t* dbits = (uint32_t*)dsm;                   // [ic][10]
    float2*   daw   = (float2*)(dsm + DA_OFF);          // [warp][20][32]
    uint32_t* smask = (uint32_t*)(dsm + SMK_OFF);       // [px][2]
    __shared__ float wh_s[3*C2];
    __shared__ float bias_s[C2];
    __shared__ float bh_s[3];

    const int tid  = threadIdx.x;
    const int warp = tid >> 5, lane = tid & 31;         // warp = row in band (0..7), lane = oc pair
    const int tx  = blockIdx.x & 7;                     // 16-col tile
    const int tyb = blockIdx.x >> 3;                    // 8-row band (0..15)
    const int b   = blockIdx.y;
    const int g0 = tx*16 - 1;
    const int w0 = g0 >> 5, off = g0 & 31;

    for (int i = tid; i < 3*C2; i += 256) wh_s[i] = Wh[i];
    if (tid < C2) bias_s[tid] = b2[tid];
    if (tid < 3)  bh_s[tid] = bh[tid];
    __syncthreads();   // bias_s/wh_s visible before register reads

    float tau = tau2p[0];
    tau = fminf(fmaxf(tau, 0.5f), 5.0f);
    const float it = 1.0f / tau;
    const float bw0 = bias_s[2*lane], bw1 = bias_s[2*lane + 1];

    const float* ybrow = g_ybase + ((size_t)b*HW + (size_t)(tyb*8 + warp)*WW + tx*16)*C2 + 2*lane;
    float2* myda = daw + (size_t)warp*20*32 + lane;     // stride 32 float2 per px idx

    float v[32];
    #pragma unroll
    for (int i = 0; i < 32; ++i) v[i] = 0.f;
    uint32_t amb = 0;
    uint32_t hist[TT];
    #pragma unroll
    for (int t = 0; t < TT; ++t) hist[t] = 0;

    for (int t = 0; t < TT; ++t) {
        __syncthreads();   // prior-t consumers of dbits/smask done
        // build delta windows: 18-bit rows, bit k = input x = tx*16-1+k; rows tyb*8-1 .. tyb*8+8
        {
            const uint32_t* src = g_sdel + (size_t)(t*BB + b)*C2*HH*4;
            for (int i = tid; i < C2*10; i += 256) {
                int ic = i / 10, y = i % 10;
                int gy = tyb*8 - 1 + y;
                uint32_t val = 0;
                if ((unsigned)gy < (unsigned)HH) {
                    const uint32_t* rowp = src + ((size_t)ic*HH + gy)*4;
                    uint32_t lo = (w0 >= 0) ? rowp[w0] : 0u;
                    uint32_t hi = (w0 + 1 <= 3) ? rowp[w0 + 1] : 0u;
                    val = __funnelshift_r(lo, hi, off);
                }
                dbits[ic*10 + y] = val;
            }
        }
        __syncthreads();

        // zero this warp's da tile (lane-private columns)
        #pragma unroll
        for (int i = 0; i < 20; ++i) myda[i*32] = make_float2(0.f, 0.f);

        // spike walk: window rows warp..warp+2, 64 ic each
        #pragma unroll
        for (int dy = 0; dy < 3; ++dy) {
            const uint32_t* wrow = dbits + (warp + dy);
            const float* wt = g_w2t + (size_t)(dy*3)*C2*C2 + 2*lane;
            #pragma unroll 1
            for (int ic = 0; ic < C2; ++ic) {
                uint32_t bits = wrow[ic*10] & 0x3FFFFu;
                if (!bits) continue;                    // single uniform branch region
                const float2 wA = __ldg((const float2*)(wt + (size_t)ic*C2));            // dx=0
                const float2 wB = __ldg((const float2*)(wt + (size_t)ic*C2 + C2*C2));    // dx=1
                const float2 wC = __ldg((const float2*)(wt + (size_t)ic*C2 + 2*C2*C2));  // dx=2
                while (bits) {                          // uniform loop over set bits
                    int k = __ffs(bits) - 1;
                    bits &= bits - 1;
                    float2 a0 = myda[(k+2)*32]; a0.x = __fadd_rn(a0.x, wA.x); a0.y = __fadd_rn(a0.y, wA.y); myda[(k+2)*32] = a0;
                    float2 a1 = myda[(k+1)*32]; a1.x = __fadd_rn(a1.x, wB.x); a1.y = __fadd_rn(a1.y, wB.y); myda[(k+1)*32] = a1;
                    float2 a2 = myda[(k  )*32]; a2.x = __fadd_rn(a2.x, wC.x); a2.y = __fadd_rn(a2.y, wC.y); myda[(k  )*32] = a2;
                }
            }
        }

        // LIF2 + spike masks
        #pragma unroll
        for (int c = 0; c < 16; ++c) {
            float2 bas = *(const float2*)(ybrow + (size_t)c*C2);
            float2 del = myda[(c+2)*32];
            int s0, s1;
            {
                const int slot = 2*c;
                float y = __fadd_rn(__fadd_rn(bas.x, del.x), bw0);
                float vv = __fadd_rn(v[slot], __fmul_rn(it, __fadd_rn(y, -v[slot])));
                float m = __fadd_rn(vv, -0.1f);
                s0 = (m >= 0.f);
                amb |= ((uint32_t)(fabsf(m) < EPS_AMB)) << slot;
                hist[t] |= ((uint32_t)s0 << slot);
                v[slot] = s0 ? 0.f : fminf(fmaxf(vv, -2.f), 2.f);
            }
            {
                const int slot = 2*c + 1;
                float y = __fadd_rn(__fadd_rn(bas.y, del.y), bw1);
                float vv = __fadd_rn(v[slot], __fmul_rn(it, __fadd_rn(y, -v[slot])));
                float m = __fadd_rn(vv, -0.1f);
                s1 = (m >= 0.f);
                amb |= ((uint32_t)(fabsf(m) < EPS_AMB)) << slot;
                hist[t] |= ((uint32_t)s1 << slot);
                v[slot] = s1 ? 0.f : fminf(fmaxf(vv, -2.f), 2.f);
            }
            uint32_t m0 = __ballot_sync(0xffffffffu, s0);
            uint32_t m1 = __ballot_sync(0xffffffffu, s1);
            if (lane == 0) {
                smask[(warp*16 + c)*2]     = m0;
                smask[(warp*16 + c)*2 + 1] = m1;
            }
        }
        __syncthreads();

        // head: 128 threads, one pixel each (ascending-oc exact chain via predicated FMA)
        if (tid < 128) {
            const int px = tid;
            uint32_t m0 = smask[px*2], m1 = smask[px*2 + 1];
            float o0 = 0.f, o1 = 0.f, o2 = 0.f;
            #pragma unroll
            for (int l = 0; l < 32; ++l) {
                float f0 = __uint_as_float(((m0 >> l) & 1u) * 0x3f800000u);
                float f1 = __uint_as_float(((m1 >> l) & 1u) * 0x3f800000u);
                o0 = fmaf(f0, wh_s[2*l], o0);
                o1 = fmaf(f0, wh_s[C2 + 2*l], o1);
                o2 = fmaf(f0, wh_s[2*C2 + 2*l], o2);
                o0 = fmaf(f1, wh_s[2*l + 1], o0);
                o1 = fmaf(f1, wh_s[C2 + 2*l + 1], o1);
                o2 = fmaf(f1, wh_s[2*C2 + 2*l + 1], o2);
            }
            const int gy = tyb*8 + (px >> 4), gx = tx*16 + (px & 15);
            size_t ob = ((size_t)(t*BB + b)*3)*HW + (size_t)gy*WW + gx;
            out[ob]        = __fadd_rn(o0, bh_s[0]);
            out[ob +  HW]  = __fadd_rn(o1, bh_s[1]);
            out[ob + 2*HW] = __fadd_rn(o2, bh_s[2]);
        }
    }

    // emit fixup records for ambiguous slots
    if (amb) {
        #pragma unroll
        for (int slot = 0; slot < 32; ++slot) {
            if ((amb >> slot) & 1u) {
                const int oc = 2*lane + (slot & 1);
                const int c  = slot >> 1;
                const int gy = tyb*8 + warp, gx = tx*16 + c;
                uint32_t sh5 = 0;
                #pragma unroll
                for (int t = 0; t < TT; ++t) sh5 |= ((hist[t] >> slot) & 1u) << t;
                uint32_t rec = (uint32_t)(gy*WW + gx) | ((uint32_t)oc << 14)
                             | ((uint32_t)b << 20) | (sh5 << 23);
                uint32_t idx = atomicAdd(&g_fixcnt, 1u);
                if (idx < FIXCAP) g_fix[idx] = rec;
            }
        }
    }
}

// ---------------- K3: warp-cooperative, ORDER-EXACT fp32 replay of ambiguous elements ----------------
__global__ __launch_bounds__(128) void k3_fixup(
    const float* __restrict__ b2,
    const float* __restrict__ Wh,
    const float* __restrict__ tau2p,
    float* __restrict__ out)
{
    uint32_t cnt = g_fixcnt;
    if (cnt > FIXCAP) cnt = FIXCAP;

    const int lane = threadIdx.x & 31;
    const uint32_t wid = (blockIdx.x * blockDim.x + threadIdx.x) >> 5;
    const uint32_t nw  = (gridDim.x * blockDim.x) >> 5;

    float tau = tau2p[0];
    tau = fminf(fmaxf(tau, 0.5f), 5.0f);
    const float it = 1.0f / tau;

    for (uint32_t i = wid; i < cnt; i += nw) {
        uint32_t rec = g_fix[i];
        int pixel = rec & 16383;
        int oc    = (rec >> 14) & 63;
        int b     = (rec >> 20) & 7;
        uint32_t sh = (rec >> 23) & 31;
        int py = pixel >> 7, px = pixel & 127;

        const int ic0 = lane, ic1 = lane + 32;
        float wt0[9], wt1[9];
        #pragma unroll
        for (int tap = 0; tap < 9; ++tap) {
            wt0[tap] = g_w2t[((size_t)tap*C2 + ic0)*C2 + oc];
            wt1[tap] = g_w2t[((size_t)tap*C2 + ic1)*C2 + oc];
        }

        const uint32_t* bbase = g_base + (size_t)b*C2*HH*4;
        float v = 0.f;
        const float bia = b2[oc];

        for (int t = 0; t < TT; ++t) {
            const uint32_t* dbase = g_sdel + (size_t)(t*BB + b)*C2*HH*4;
            float acc = 0.f;
            #pragma unroll
            for (int tap = 0; tap < 9; ++tap) {
                int dy = tap / 3, dx = tap % 3;
                int gy = py + dy - 1, gx = px + dx - 1;
                if ((unsigned)gy < (unsigned)HH && (unsigned)gx < (unsigned)WW) {
                    int wi = gx >> 5, offb = gx & 31;
                    size_t ro = (size_t)gy*4 + wi;
                    uint32_t wd0 = bbase[(size_t)ic0*HH*4 + ro] | dbase[(size_t)ic0*HH*4 + ro];
                    uint32_t wd1 = bbase[(size_t)ic1*HH*4 + ro] | dbase[(size_t)ic1*HH*4 + ro];
                    uint32_t m0 = __ballot_sync(0xffffffffu, (wd0 >> offb) & 1u);
                    uint32_t m1 = __ballot_sync(0xffffffffu, (wd1 >> offb) & 1u);
                    while (m0) {            // uniform: ascending ic 0..31
                        int j = __ffs(m0) - 1; m0 &= m0 - 1;
                        float w = __shfl_sync(0xffffffffu, wt0[tap], j);
                        acc = __fadd_rn(acc, w);
                    }
                    while (m1) {            // uniform: ascending ic 32..63
                        int j = __ffs(m1) - 1; m1 &= m1 - 1;
                        float w = __shfl_sync(0xffffffffu, wt1[tap], j);
                        acc = __fadd_rn(acc, w);
                    }
                }
            }
            float y = __fadd_rn(acc, bia);
            float vv = __fadd_rn(v, __fmul_rn(it, __fadd_rn(y, -v)));
            int s = (__fadd_rn(vv, -0.1f) >= 0.f);
            v = s ? 0.f : fminf(fmaxf(vv, -2.f), 2.f);

            int s_h = (sh >> t) & 1;
            if (s != s_h && lane == 0) {
                float d = s ? 1.f : -1.f;
                #pragma unroll
                for (int ch = 0; ch < 3; ++ch)
                    atomicAdd(&out[((size_t)(t*BB + b)*3 + ch)*HW + pixel], d * Wh[ch*C2 + oc]);
            }
        }
    }
}

// ---------------- launch ----------------
extern "C" void kernel_launch(void* const* d_in, const int* in_sizes, int n_in,
                              void* d_out, int out_size)
{
    const float* lr_lab = (const float*)d_in[0];
    const float* W1     = (const float*)d_in[1];
    const float* b1     = (const float*)d_in[2];
    const float* tau1   = (const float*)d_in[3];
    const float* W2     = (const float*)d_in[4];
    const float* b2     = (const float*)d_in[5];
    const float* tau2   = (const float*)d_in[6];
    const float* Wh     = (const float*)d_in[7];
    const float* bh     = (const float*)d_in[8];
    float* out = (float*)d_out;

    cudaFuncSetAttribute(k2b_fused, cudaFuncAttributeMaxDynamicSharedMemorySize, SMEM_K2B);

    k0_pack<<<(9*C2*C2 + 255)/256, 256>>>(W2);
    k1_conv1_lif1<<<dim3(64, BB), 256>>>(lr_lab, W1, b1, tau1);
    k2a_base<<<dim3(64, BB), 256>>>();
    k2b_fused<<<dim3(128, BB), 256, SMEM_K2B>>>(b2, Wh, bh, tau2, out);
    k3_fixup<<<2048, 128>>>(b2, Wh, tau2, out);
}

// round 17
// speedup vs baseline: 1.2308x; 1.1151x over previous
#include <cuda_runtime.h>
#include <stdint.h>

// Fixed problem shapes
#define TT 5
#define BB 8
#define HH 128
#define WW 128
#define HW (HH*WW)
#define C1 3
#define C2 64

#define EPS_AMB 5e-5f
#define FIXCAP (1u<<21)

// ---------------- static scratch ----------------
__device__ __align__(16) uint32_t g_base[(size_t)BB*C2*HH*4];        // AND-of-5 spike bitplanes (1 MB)
__device__ __align__(16) uint32_t g_sdel[(size_t)TT*BB*C2*HH*4];     // delta bitplanes per t (5.2 MB)
__device__ __align__(16) float    g_w2t[9*C2*C2];                    // [tap][ic][oc] fp32
__device__ __align__(16) float    g_ybase[(size_t)BB*HW*C2];         // base conv result [b][px][oc] (33.5 MB)
__device__ uint32_t g_fixcnt;
__device__ uint32_t g_fix[FIXCAP];

// ---------------- K0: W2 [oc][ic][tap] -> [tap][ic][oc] + reset counter ----------------
__global__ void k0_pack(const float* __restrict__ W2) {
    int i = blockIdx.x * 256 + threadIdx.x;
    if (i == 0) g_fixcnt = 0;
    if (i < 9*C2*C2) {
        int oc  = i / (C2*9);
        int r   = i % (C2*9);
        int ic  = r / 9;
        int tap = r % 9;
        g_w2t[(tap*C2 + ic)*C2 + oc] = W2[i];
    }
}

// ---------------- K1: conv1 + 5-step LIF1 -> base/delta bitplanes ----------------
__global__ __launch_bounds__(256) void k1_conv1_lif1(
    const float* __restrict__ x,
    const float* __restrict__ W1,
    const float* __restrict__ b1,
    const float* __restrict__ tau1p)
{
    __shared__ __align__(16) float xs[C1][10][36];
    __shared__ __align__(16) float ws[27][C2];
    __shared__ float bs[C2];

    const int tid = threadIdx.x;
    const int tx = blockIdx.x & 3;
    const int ty = blockIdx.x >> 2;
    const int b  = blockIdx.y;

    for (int i = tid; i < C2*27; i += 256) {
        int o = i / 27, r = i % 27;
        int c = r / 9, t9 = r % 9;
        ws[t9*3 + c][o] = W1[i];
    }
    if (tid < C2) bs[tid] = b1[tid];

    for (int i = tid; i < C1*10*34; i += 256) {
        int c = i / 340, r = i % 340, y = r / 34, xc = r % 34;
        int gy = ty*8 - 1 + y, gx = tx*32 - 1 + xc;
        float v = 0.f;
        if ((unsigned)gy < (unsigned)HH && (unsigned)gx < (unsigned)WW)
            v = x[((size_t)b*C1 + c)*HW + gy*WW + gx];
        xs[c][y][xc] = v;
    }
    __syncthreads();

    const int px = tid & 31, py = tid >> 5;

    float acc[C2];
    #pragma unroll
    for (int o = 0; o < C2; ++o) acc[o] = 0.f;

    #pragma unroll
    for (int dy = 0; dy < 3; ++dy)
        #pragma unroll
        for (int dx = 0; dx < 3; ++dx)
            #pragma unroll
            for (int c = 0; c < C1; ++c) {
                float xv = xs[c][py+dy][px+dx];
                const float4* wp = (const float4*)&ws[(dy*3+dx)*3 + c][0];
                #pragma unroll
                for (int q = 0; q < 16; ++q) {
                    float4 w = wp[q];
                    acc[q*4+0] = fmaf(w.x, xv, acc[q*4+0]);
                    acc[q*4+1] = fmaf(w.y, xv, acc[q*4+1]);
                    acc[q*4+2] = fmaf(w.z, xv, acc[q*4+2]);
                    acc[q*4+3] = fmaf(w.w, xv, acc[q*4+3]);
                }
            }

    float tau = tau1p[0];
    tau = fminf(fmaxf(tau, 0.5f), 5.0f);
    const float it = 1.0f / tau;
    const int gy = ty*8 + py;

    #pragma unroll
    for (int o = 0; o < C2; ++o) {
        const float xo = __fadd_rn(acc[o], bs[o]);
        float v = 0.f;
        uint32_t sh5 = 0;
        #pragma unroll
        for (int t = 0; t < TT; ++t) {
            v = __fadd_rn(v, __fmul_rn(it, __fadd_rn(xo, -v)));
            int s = (__fadd_rn(v, -0.1f) >= 0.f);
            v = s ? 0.f : fminf(fmaxf(v, -2.f), 2.f);
            sh5 |= (uint32_t)s << t;
        }
        uint32_t bsbit = (sh5 == 0x1Fu) ? 1u : 0u;
        uint32_t bw = __ballot_sync(0xffffffffu, bsbit);
        if (px == 0)
            g_base[((size_t)b*C2 + o)*HH*4 + (size_t)gy*4 + tx] = bw;
        #pragma unroll
        for (int t = 0; t < TT; ++t) {
            uint32_t db = ((sh5 >> t) & 1u) & (bsbit ^ 1u);
            uint32_t dw = __ballot_sync(0xffffffffu, db);
            if (px == 0)
                g_sdel[(((size_t)t*BB + b)*C2 + o)*HH*4 + (size_t)gy*4 + tx] = dw;
        }
    }
}

// ---------------- K2a: dense base conv (once), R4 engine ----------------
__global__ __launch_bounds__(256, 2) void k2a_base(void)
{
    __shared__ uint32_t sbits[C2*18];
    __shared__ __align__(16) float wbuf[C2*C2];

    const int tid  = threadIdx.x;
    const int warp = tid >> 5, lane = tid & 31;
    const int py  = lane >> 1;
    const int pxb = (lane & 1) * 8;
    const int ocg = warp;
    const int tx = blockIdx.x & 7, ty = blockIdx.x >> 3;
    const int b  = blockIdx.y;
    const int g0 = tx*16 - 1;
    const int w0 = g0 >> 5, off = g0 & 31;

    {
        const uint32_t* src = g_base + (size_t)b*C2*HH*4;
        for (int i = tid; i < C2*18; i += 256) {
            int ic = i / 18, y = i % 18;
            int gy = ty*16 - 1 + y;
            uint32_t val = 0;
            if ((unsigned)gy < (unsigned)HH) {
                const uint32_t* rowp = src + ((size_t)ic*HH + gy)*4;
                uint32_t lo = (w0 >= 0) ? rowp[w0] : 0u;
                uint32_t hi = (w0 + 1 <= 3) ? rowp[w0 + 1] : 0u;
                val = __funnelshift_r(lo, hi, off);
            }
            sbits[ic*18 + y] = val;
        }
    }

    float acc[64];
    #pragma unroll
    for (int i = 0; i < 64; ++i) acc[i] = 0.f;

    uint4 p0, p1, p2, p3;
    {
        const uint4* src = (const uint4*)g_w2t;
        p0 = src[tid*4]; p1 = src[tid*4+1]; p2 = src[tid*4+2]; p3 = src[tid*4+3];
    }

    for (int tap = 0; tap < 9; ++tap) {
        __syncthreads();
        ((uint4*)wbuf)[tid*4]   = p0;
        ((uint4*)wbuf)[tid*4+1] = p1;
        ((uint4*)wbuf)[tid*4+2] = p2;
        ((uint4*)wbuf)[tid*4+3] = p3;
        __syncthreads();
        if (tap < 8) {
            const uint4* src = (const uint4*)(g_w2t + (size_t)(tap+1)*C2*C2);
            p0 = src[tid*4]; p1 = src[tid*4+1]; p2 = src[tid*4+2]; p3 = src[tid*4+3];
        }

        const int dy = tap / 3, dx = tap % 3;
        const int sh = pxb + dx;
        const uint32_t* srow = sbits + (py + dy);
        const float* wt = wbuf + ocg*8;

        #pragma unroll 4
        for (int ic = 0; ic < C2; ++ic) {
            uint32_t bbits2 = srow[ic*18] >> sh;
            const float4* wp = (const float4*)(wt + ic*C2);
            float4 wa = wp[0], wb = wp[1];
            float wv[8] = {wa.x, wa.y, wa.z, wa.w, wb.x, wb.y, wb.z, wb.w};

            float sf[8];
            #pragma unroll
            for (int j = 0; j < 8; ++j)
                sf[j] = __uint_as_float(((bbits2 >> j) & 1u) * 0x3f800000u);

            #pragma unroll
            for (int o = 0; o < 8; ++o) {
                float w = wv[o];
                #pragma unroll
                for (int j = 0; j < 8; ++j)
                    acc[o*8 + j] = fmaf(w, sf[j], acc[o*8 + j]);
            }
        }
    }

    const int gy = ty*16 + py, gx0 = tx*16 + pxb;
    #pragma unroll
    for (int j = 0; j < 8; ++j) {
        float* dst = g_ybase + ((size_t)b*HW + (size_t)gy*WW + gx0 + j)*C2 + ocg*8;
        float4 r0 = make_float4(acc[0*8+j], acc[1*8+j], acc[2*8+j], acc[3*8+j]);
        float4 r1 = make_float4(acc[4*8+j], acc[5*8+j], acc[6*8+j], acc[7*8+j]);
        *(float4*)dst       = r0;
        *(float4*)(dst + 4) = r1;
    }
}

// ---------------- K2b: compacted spike-list delta conv + LIF2 + head ----------------
// block 256 (8 warps = 8 rows), grid (128 tiles, 8 b)
// dynamic smem: rowlist [10][64] u32 (2560B) | rowcnt [16] (64B) | da [8][20][32] float2 (40960B) | smask (1024B)
#define RC_OFF  2560
#define DA_OFF  2624
#define SMK_OFF (DA_OFF + 8*20*32*8)
#define SMEM_K2B (SMK_OFF + 1024)

__global__ __launch_bounds__(256, 4) void k2b_fused(
    const float* __restrict__ b2,
    const float* __restrict__ Wh,    // [3][64]
    const float* __restrict__ bh,
    const float* __restrict__ tau2p,
    float* __restrict__ out)         // [T,B,3,128,128]
{
    extern __shared__ __align__(16) uint8_t dsm[];
    uint32_t* rowlist = (uint32_t*)dsm;                 // [y][64] entries (ic<<18)|bits
    uint32_t* rowcnt  = (uint32_t*)(dsm + RC_OFF);      // [10]
    float2*   daw     = (float2*)(dsm + DA_OFF);        // [warp][20][32]
    uint32_t* smask   = (uint32_t*)(dsm + SMK_OFF);     // [px][2]
    __shared__ float wh_s[3*C2];
    __shared__ float bias_s[C2];
    __shared__ float bh_s[3];

    const int tid  = threadIdx.x;
    const int warp = tid >> 5, lane = tid & 31;         // warp = row in band (0..7), lane = oc pair
    const int tx  = blockIdx.x & 7;
    const int tyb = blockIdx.x >> 3;
    const int b   = blockIdx.y;
    const int g0 = tx*16 - 1;
    const int w0 = g0 >> 5, off = g0 & 31;

    for (int i = tid; i < 3*C2; i += 256) wh_s[i] = Wh[i];
    if (tid < C2) bias_s[tid] = b2[tid];
    if (tid < 3)  bh_s[tid] = bh[tid];
    __syncthreads();   // bias_s/wh_s visible before register reads

    float tau = tau2p[0];
    tau = fminf(fmaxf(tau, 0.5f), 5.0f);
    const float it = 1.0f / tau;
    const float bw0 = bias_s[2*lane], bw1 = bias_s[2*lane + 1];

    const float* ybrow = g_ybase + ((size_t)b*HW + (size_t)(tyb*8 + warp)*WW + tx*16)*C2 + 2*lane;
    float2* myda = daw + (size_t)warp*20*32 + lane;

    float v[32];
    #pragma unroll
    for (int i = 0; i < 32; ++i) v[i] = 0.f;
    uint32_t amb = 0;
    uint32_t hist[TT];
    #pragma unroll
    for (int t = 0; t < TT; ++t) hist[t] = 0;

    for (int t = 0; t < TT; ++t) {
        __syncthreads();   // prior-t consumers of rowlist/smask done
        if (tid < 10) rowcnt[tid] = 0;
        __syncthreads();
        // build compacted nonzero-window lists: entry = (ic<<18) | 18-bit window
        {
            const uint32_t* src = g_sdel + (size_t)(t*BB + b)*C2*HH*4;
            for (int i = tid; i < C2*10; i += 256) {
                int ic = i / 10, y = i % 10;
                int gy = tyb*8 - 1 + y;
                uint32_t val = 0;
                if ((unsigned)gy < (unsigned)HH) {
                    const uint32_t* rowp = src + ((size_t)ic*HH + gy)*4;
                    uint32_t lo = (w0 >= 0) ? rowp[w0] : 0u;
                    uint32_t hi = (w0 + 1 <= 3) ? rowp[w0 + 1] : 0u;
                    val = __funnelshift_r(lo, hi, off) & 0x3FFFFu;
                }
                if (val) {
                    uint32_t pos = atomicAdd(&rowcnt[y], 1u);
                    rowlist[y*64 + pos] = ((uint32_t)ic << 18) | val;
                }
            }
        }
        __syncthreads();

        // zero this warp's da tile (lane-private columns)
        #pragma unroll
        for (int i = 0; i < 20; ++i) myda[i*32] = make_float2(0.f, 0.f);

        // spike walk over compacted lists: rows warp..warp+2
        #pragma unroll
        for (int dy = 0; dy < 3; ++dy) {
            const int y = warp + dy;
            const int cnt = rowcnt[y];
            const uint32_t* rl = rowlist + y*64;
            const float* wt = g_w2t + (size_t)(dy*3)*C2*C2 + 2*lane;
            #pragma unroll 1
            for (int ii = 0; ii < cnt; ++ii) {
                uint32_t e = rl[ii];
                int ic = e >> 18;
                uint32_t bits = e & 0x3FFFFu;
                const float2 wA = __ldg((const float2*)(wt + (size_t)ic*C2));            // dx=0
                const float2 wB = __ldg((const float2*)(wt + (size_t)ic*C2 + C2*C2));    // dx=1
                const float2 wC = __ldg((const float2*)(wt + (size_t)ic*C2 + 2*C2*C2));  // dx=2
                while (bits) {
                    int k = __ffs(bits) - 1;
                    bits &= bits - 1;
                    float2 a0 = myda[(k+2)*32]; a0.x = __fadd_rn(a0.x, wA.x); a0.y = __fadd_rn(a0.y, wA.y); myda[(k+2)*32] = a0;
                    float2 a1 = myda[(k+1)*32]; a1.x = __fadd_rn(a1.x, wB.x); a1.y = __fadd_rn(a1.y, wB.y); myda[(k+1)*32] = a1;
                    float2 a2 = myda[(k  )*32]; a2.x = __fadd_rn(a2.x, wC.x); a2.y = __fadd_rn(a2.y, wC.y); myda[(k  )*32] = a2;
                }
            }
        }

        // LIF2 + spike masks
        #pragma unroll
        for (int c = 0; c < 16; ++c) {
            float2 bas = *(const float2*)(ybrow + (size_t)c*C2);
            float2 del = myda[(c+2)*32];
            int s0, s1;
            {
                const int slot = 2*c;
                float y = __fadd_rn(__fadd_rn(bas.x, del.x), bw0);
                float vv = __fadd_rn(v[slot], __fmul_rn(it, __fadd_rn(y, -v[slot])));
                float m = __fadd_rn(vv, -0.1f);
                s0 = (m >= 0.f);
                amb |= ((uint32_t)(fabsf(m) < EPS_AMB)) << slot;
                hist[t] |= ((uint32_t)s0 << slot);
                v[slot] = s0 ? 0.f : fminf(fmaxf(vv, -2.f), 2.f);
            }
            {
                const int slot = 2*c + 1;
                float y = __fadd_rn(__fadd_rn(bas.y, del.y), bw1);
                float vv = __fadd_rn(v[slot], __fmul_rn(it, __fadd_rn(y, -v[slot])));
                float m = __fadd_rn(vv, -0.1f);
                s1 = (m >= 0.f);
                amb |= ((uint32_t)(fabsf(m) < EPS_AMB)) << slot;
                hist[t] |= ((uint32_t)s1 << slot);
                v[slot] = s1 ? 0.f : fminf(fmaxf(vv, -2.f), 2.f);
            }
            uint32_t m0 = __ballot_sync(0xffffffffu, s0);
            uint32_t m1 = __ballot_sync(0xffffffffu, s1);
            if (lane == 0) {
                smask[(warp*16 + c)*2]     = m0;
                smask[(warp*16 + c)*2 + 1] = m1;
            }
        }
        __syncthreads();

        // head: 128 threads, one pixel each (ascending-oc exact chain via predicated FMA)
        if (tid < 128) {
            const int px = tid;
            uint32_t m0 = smask[px*2], m1 = smask[px*2 + 1];
            float o0 = 0.f, o1 = 0.f, o2 = 0.f;
            #pragma unroll
            for (int l = 0; l < 32; ++l) {
                float f0 = __uint_as_float(((m0 >> l) & 1u) * 0x3f800000u);
                float f1 = __uint_as_float(((m1 >> l) & 1u) * 0x3f800000u);
                o0 = fmaf(f0, wh_s[2*l], o0);
                o1 = fmaf(f0, wh_s[C2 + 2*l], o1);
                o2 = fmaf(f0, wh_s[2*C2 + 2*l], o2);
                o0 = fmaf(f1, wh_s[2*l + 1], o0);
                o1 = fmaf(f1, wh_s[C2 + 2*l + 1], o1);
                o2 = fmaf(f1, wh_s[2*C2 + 2*l + 1], o2);
            }
            const int gy = tyb*8 + (px >> 4), gx = tx*16 + (px & 15);
            size_t ob = ((size_t)(t*BB + b)*3)*HW + (size_t)gy*WW + gx;
            out[ob]        = __fadd_rn(o0, bh_s[0]);
            out[ob +  HW]  = __fadd_rn(o1, bh_s[1]);
            out[ob + 2*HW] = __fadd_rn(o2, bh_s[2]);
        }
    }

    // emit fixup records for ambiguous slots
    if (amb) {
        #pragma unroll
        for (int slot = 0; slot < 32; ++slot) {
            if ((amb >> slot) & 1u) {
                const int oc = 2*lane + (slot & 1);
                const int c  = slot >> 1;
                const int gy = tyb*8 + warp, gx = tx*16 + c;
                uint32_t sh5 = 0;
                #pragma unroll
                for (int t = 0; t < TT; ++t) sh5 |= ((hist[t] >> slot) & 1u) << t;
                uint32_t rec = (uint32_t)(gy*WW + gx) | ((uint32_t)oc << 14)
                             | ((uint32_t)b << 20) | (sh5 << 23);
                uint32_t idx = atomicAdd(&g_fixcnt, 1u);
                if (idx < FIXCAP) g_fix[idx] = rec;
            }
        }
    }
}

// ---------------- K3: warp-cooperative, ORDER-EXACT fp32 replay (base words hoisted) ----------------
__global__ __launch_bounds__(128) void k3_fixup(
    const float* __restrict__ b2,
    const float* __restrict__ Wh,
    const float* __restrict__ tau2p,
    float* __restrict__ out)
{
    uint32_t cnt = g_fixcnt;
    if (cnt > FIXCAP) cnt = FIXCAP;

    const int lane = threadIdx.x & 31;
    const uint32_t wid = (blockIdx.x * blockDim.x + threadIdx.x) >> 5;
    const uint32_t nw  = (gridDim.x * blockDim.x) >> 5;

    float tau = tau2p[0];
    tau = fminf(fmaxf(tau, 0.5f), 5.0f);
    const float it = 1.0f / tau;

    for (uint32_t i = wid; i < cnt; i += nw) {
        uint32_t rec = g_fix[i];
        int pixel = rec & 16383;
        int oc    = (rec >> 14) & 63;
        int b     = (rec >> 20) & 7;
        uint32_t sh = (rec >> 23) & 31;
        int py = pixel >> 7, px = pixel & 127;

        const int ic0 = lane, ic1 = lane + 32;
        float wt0[9], wt1[9];
        uint32_t bwd0[9], bwd1[9];
        uint32_t inb[9];
        size_t ro_[9];
        int offb_[9];
        const uint32_t* bbase = g_base + (size_t)b*C2*HH*4;
        #pragma unroll
        for (int tap = 0; tap < 9; ++tap) {
            wt0[tap] = g_w2t[((size_t)tap*C2 + ic0)*C2 + oc];
            wt1[tap] = g_w2t[((size_t)tap*C2 + ic1)*C2 + oc];
            int dy = tap / 3, dx = tap % 3;
            int gy = py + dy - 1, gx = px + dx - 1;
            bool ok = ((unsigned)gy < (unsigned)HH) && ((unsigned)gx < (unsigned)WW);
            inb[tap] = ok;
            if (ok) {
                ro_[tap] = (size_t)gy*4 + (gx >> 5);
                offb_[tap] = gx & 31;
                bwd0[tap] = bbase[(size_t)ic0*HH*4 + ro_[tap]];
                bwd1[tap] = bbase[(size_t)ic1*HH*4 + ro_[tap]];
            } else {
                ro_[tap] = 0; offb_[tap] = 0; bwd0[tap] = 0; bwd1[tap] = 0;
            }
        }

        float v = 0.f;
        const float bia = b2[oc];

        for (int t = 0; t < TT; ++t) {
            const uint32_t* dbase = g_sdel + (size_t)(t*BB + b)*C2*HH*4;
            float acc = 0.f;
            #pragma unroll
            for (int tap = 0; tap < 9; ++tap) {
                if (inb[tap]) {
                    uint32_t wd0 = bwd0[tap] | dbase[(size_t)ic0*HH*4 + ro_[tap]];
                    uint32_t wd1 = bwd1[tap] | dbase[(size_t)ic1*HH*4 + ro_[tap]];
                    int offb = offb_[tap];
                    uint32_t m0 = __ballot_sync(0xffffffffu, (wd0 >> offb) & 1u);
                    uint32_t m1 = __ballot_sync(0xffffffffu, (wd1 >> offb) & 1u);
                    while (m0) {            // uniform: ascending ic 0..31
                        int j = __ffs(m0) - 1; m0 &= m0 - 1;
                        float w = __shfl_sync(0xffffffffu, wt0[tap], j);
                        acc = __fadd_rn(acc, w);
                    }
                    while (m1) {            // uniform: ascending ic 32..63
                        int j = __ffs(m1) - 1; m1 &= m1 - 1;
                        float w = __shfl_sync(0xffffffffu, wt1[tap], j);
                        acc = __fadd_rn(acc, w);
                    }
                } else {
                    __ballot_sync(0xffffffffu, 0);   // keep warp convergent pattern harmless
                }
            }
            float y = __fadd_rn(acc, bia);
            float vv = __fadd_rn(v, __fmul_rn(it, __fadd_rn(y, -v)));
            int s = (__fadd_rn(vv, -0.1f) >= 0.f);
            v = s ? 0.f : fminf(fmaxf(vv, -2.f), 2.f);

            int s_h = (sh >> t) & 1;
            if (s != s_h && lane == 0) {
                float d = s ? 1.f : -1.f;
                #pragma unroll
                for (int ch = 0; ch < 3; ++ch)
                    atomicAdd(&out[((size_t)(t*BB + b)*3 + ch)*HW + pixel], d * Wh[ch*C2 + oc]);
            }
        }
    }
}

// ---------------- launch ----------------
extern "C" void kernel_launch(void* const* d_in, const int* in_sizes, int n_in,
                              void* d_out, int out_size)
{
    const float* lr_lab = (const float*)d_in[0];
    const float* W1     = (const float*)d_in[1];
    const float* b1     = (const float*)d_in[2];
    const float* tau1   = (const float*)d_in[3];
    const float* W2     = (const float*)d_in[4];
    const float* b2     = (const float*)d_in[5];
    const float* tau2   = (const float*)d_in[6];
    const float* Wh     = (const float*)d_in[7];
    const float* bh     = (const float*)d_in[8];
    float* out = (float*)d_out;

    cudaFuncSetAttribute(k2b_fused, cudaFuncAttributeMaxDynamicSharedMemorySize, SMEM_K2B);

    k0_pack<<<(9*C2*C2 + 255)/256, 256>>>(W2);
    k1_conv1_lif1<<<dim3(64, BB), 256>>>(lr_lab, W1, b1, tau1);
    k2a_base<<<dim3(64, BB), 256>>>();
    k2b_fused<<<dim3(128, BB), 256, SMEM_K2B>>>(b2, Wh, bh, tau2, out);
    k3_fixup<<<2048, 128>>>(b2, Wh, tau2, out);
}